// round 6
// baseline (speedup 1.0000x reference)
#include <cuda_runtime.h>
#include <cuda_bf16.h>
#include <cstdint>

#define N_NODES  100000
#define N_EDGES  600000
#define N_GRAPHS 2000
#define HID      128
#define LAYERS   6
#define SA       136      // bf16 row stride for smem tiles
#define NODES_PB 64       // nodes per MLP block
#define SCAN_B   1024
#define SCAN_NB  ((N_NODES + SCAN_B - 1) / SCAN_B)   // 98

// ---------------------------------------------------------------------------
// Persistent scratch (allocation-free)
// ---------------------------------------------------------------------------
__device__ float g_x  [(size_t)N_NODES * HID];
__device__ float g_agg[(size_t)N_NODES * HID];
__device__ __align__(16) __nv_bfloat16 g_wt[(size_t)2 * 2 * LAYERS * HID * SA];
// CSR scratch
__device__ int g_deg[N_NODES];
__device__ int g_rowstart[N_NODES + 1];
__device__ int g_cursor[N_NODES];
__device__ int g_blocksum[SCAN_NB];
__device__ int g_csr[N_EDGES];

// ---------------------------------------------------------------------------
// Embedding lookup
// ---------------------------------------------------------------------------
__global__ void embed_kernel(const int* __restrict__ tok,
                             const float* __restrict__ emb) {
    int i = blockIdx.x * blockDim.x + threadIdx.x;
    if (i >= N_NODES * 32) return;
    int node = i >> 5, d = i & 31;
    int t = tok[node];
    ((float4*)g_x)[i] = ((const float4*)emb)[t * 32 + d];
}

// ---------------------------------------------------------------------------
// CSR build: zero -> hist -> scan(3) -> fill
// ---------------------------------------------------------------------------
__global__ void k_zero() {
    int i = blockIdx.x * blockDim.x + threadIdx.x;
    if (i < N_NODES) g_deg[i] = 0;
}
__global__ void k_hist(const int* __restrict__ ei) {
    int i = blockIdx.x * blockDim.x + threadIdx.x;
    if (i < N_EDGES) atomicAdd(&g_deg[ei[N_EDGES + i]], 1);
}
__global__ void k_scan1() {
    __shared__ int sm[SCAN_B];
    int tid = threadIdx.x;
    int i = blockIdx.x * SCAN_B + tid;
    int v = (i < N_NODES) ? g_deg[i] : 0;
    sm[tid] = v;
    __syncthreads();
#pragma unroll
    for (int o = 1; o < SCAN_B; o <<= 1) {
        int t = (tid >= o) ? sm[tid - o] : 0;
        __syncthreads();
        sm[tid] += t;
        __syncthreads();
    }
    if (i < N_NODES) g_rowstart[i] = sm[tid] - v;   // exclusive prefix
    if (tid == SCAN_B - 1) g_blocksum[blockIdx.x] = sm[tid];
}
__global__ void k_scan2() {
    if (threadIdx.x == 0) {
        int run = 0;
        for (int b = 0; b < SCAN_NB; b++) {
            int t = g_blocksum[b];
            g_blocksum[b] = run;
            run += t;
        }
        g_rowstart[N_NODES] = run;
    }
}
__global__ void k_scan3() {
    int i = blockIdx.x * blockDim.x + threadIdx.x;
    if (i < N_NODES) {
        int r = g_rowstart[i] + g_blocksum[i / SCAN_B];
        g_rowstart[i] = r;
        g_cursor[i] = r;
    }
}
__global__ void k_fill(const int* __restrict__ ei) {
    int i = blockIdx.x * blockDim.x + threadIdx.x;
    if (i < N_EDGES) {
        int dst = ei[N_EDGES + i];
        int p = atomicAdd(&g_cursor[dst], 1);
        g_csr[p] = ei[i];
    }
}

// ---------------------------------------------------------------------------
// Gather (replaces atomic scatter): warp per node, lane = col quad.
// agg[n] = x[n] + sum_{e in row(n)} x[csr_src[e]]
// ---------------------------------------------------------------------------
__global__ void gather_kernel() {
    int w = (blockIdx.x * blockDim.x + threadIdx.x) >> 5;
    int lane = threadIdx.x & 31;
    if (w >= N_NODES) return;
    int s = __ldg(g_rowstart + w), e = __ldg(g_rowstart + w + 1);
    const float4* x4 = (const float4*)g_x;
    float4 v = x4[(size_t)w * 32 + lane];
    for (int i = s; i < e; i++) {
        int src = __ldg(g_csr + i);
        float4 u = x4[(size_t)src * 32 + lane];
        v.x += u.x; v.y += u.y; v.z += u.z; v.w += u.w;
    }
    ((float4*)g_agg)[(size_t)w * 32 + lane] = v;
}

// ---------------------------------------------------------------------------
// Weight prep: split W[k][c] into bf16 hi/lo, store transposed Wt[c][k].
// ---------------------------------------------------------------------------
__global__ void prep_w(const float* __restrict__ W1, const float* __restrict__ W2) {
    int i = blockIdx.x * blockDim.x + threadIdx.x;
    if (i >= 2 * LAYERS * HID * HID) return;
    int which = i / (LAYERS * HID * HID);
    int r = i % (LAYERS * HID * HID);
    int l = r / (HID * HID);
    int kc = r % (HID * HID);
    int k = kc / HID, c = kc % HID;
    const float* W = which ? W2 : W1;
    float v = W[(size_t)l * HID * HID + k * HID + c];
    __nv_bfloat16 hi = __float2bfloat16(v);
    __nv_bfloat16 lo = __float2bfloat16(v - __bfloat162float(hi));
    size_t img = (size_t)which * LAYERS + l;
    size_t o = img * HID * SA + (size_t)c * SA + k;
    g_wt[o] = hi;
    g_wt[(size_t)2 * LAYERS * HID * SA + o] = lo;
}

// ---------------------------------------------------------------------------
// mma.sync helpers
// ---------------------------------------------------------------------------
__device__ __forceinline__ uint32_t smem_u32(const void* p) {
    uint32_t a;
    asm("{ .reg .u64 t; cvta.to.shared.u64 t, %1; cvt.u32.u64 %0, t; }"
        : "=r"(a) : "l"(p));
    return a;
}
__device__ __forceinline__ void ldm_x4(uint32_t (&r)[4], uint32_t addr) {
    asm volatile("ldmatrix.sync.aligned.m8n8.x4.shared.b16 {%0,%1,%2,%3}, [%4];"
                 : "=r"(r[0]), "=r"(r[1]), "=r"(r[2]), "=r"(r[3]) : "r"(addr));
}
__device__ __forceinline__ void mma16816(float (&d)[4], const uint32_t (&a)[4],
                                         uint32_t b0, uint32_t b1) {
    asm volatile(
        "mma.sync.aligned.m16n8k16.row.col.f32.bf16.bf16.f32 "
        "{%0,%1,%2,%3}, {%4,%5,%6,%7}, {%8,%9}, {%0,%1,%2,%3};"
        : "+f"(d[0]), "+f"(d[1]), "+f"(d[2]), "+f"(d[3])
        : "r"(a[0]), "r"(a[1]), "r"(a[2]), "r"(a[3]), "r"(b0), "r"(b1));
}
__device__ __forceinline__ uint32_t pk(__nv_bfloat16 a, __nv_bfloat16 b) {
    return (uint32_t)__bfloat16_as_ushort(a) |
           ((uint32_t)__bfloat16_as_ushort(b) << 16);
}

// ---------------------------------------------------------------------------
// Fused GIN MLP: 64 nodes/block, 256 threads (8 warps, warp tile 32x32),
// 2 blocks/SM for phase overlap. A(hi/lo) resident; W1 then W2 staged.
// ---------------------------------------------------------------------------
#define WTILE_B  (HID * SA * 2)                   // 34816 B
#define ATILE_B  (NODES_PB * SA * 2)              // 17408 B (64 rows, one tile)
#define SMEM_BYTES (2 * ATILE_B + 2 * WTILE_B)    // 104448

// 3-product split GEMM over a 32x32 warp tile.
__device__ __forceinline__ void gemm_warp(
    uint32_t aAhi, uint32_t aAlo, uint32_t aWh, uint32_t aWl,
    int m0, int n0, int arow_off, int akoff, int brow_off, int bkoff,
    float (&acc)[2][4][4])
{
#pragma unroll
    for (int kb = 0; kb < HID; kb += 16) {
        uint32_t ah[2][4], al[2][4];
#pragma unroll
        for (int s = 0; s < 2; s++) {
            uint32_t ro = (uint32_t)((m0 + s * 16 + arow_off) * SA + kb + akoff) * 2;
            ldm_x4(ah[s], aAhi + ro);
            ldm_x4(al[s], aAlo + ro);
        }
#pragma unroll
        for (int nb = 0; nb < 2; nb++) {
            uint32_t bh[4], bl[4];
            uint32_t ro = (uint32_t)((n0 + nb * 16 + brow_off) * SA + kb + bkoff) * 2;
            ldm_x4(bh, aWh + ro);
            ldm_x4(bl, aWl + ro);
#pragma unroll
            for (int s = 0; s < 2; s++) {
                mma16816(acc[s][2 * nb],     ah[s], bh[0], bh[1]);
                mma16816(acc[s][2 * nb],     ah[s], bl[0], bl[1]);
                mma16816(acc[s][2 * nb],     al[s], bh[0], bh[1]);
                mma16816(acc[s][2 * nb + 1], ah[s], bh[2], bh[3]);
                mma16816(acc[s][2 * nb + 1], ah[s], bl[2], bl[3]);
                mma16816(acc[s][2 * nb + 1], al[s], bh[2], bh[3]);
            }
        }
    }
}

__global__ void __launch_bounds__(256, 2) mlp_mma(
    const float* __restrict__ b1, const float* __restrict__ b2, int l)
{
    extern __shared__ __align__(16) char S[];
    char* pAhi = S;                       // 64 x SA bf16
    char* pAlo = S + ATILE_B;
    char* pWh  = S + 2 * ATILE_B;         // staged W1 then W2
    char* pWl  = S + 2 * ATILE_B + WTILE_B;
    uint32_t aAhi = smem_u32(pAhi);
    uint32_t aAlo = aAhi + ATILE_B;
    uint32_t aWh  = aAhi + 2 * ATILE_B;
    uint32_t aWl  = aWh + WTILE_B;

    int tid = threadIdx.x, warp = tid >> 5, lane = tid & 31;
    int node0 = blockIdx.x * NODES_PB;

    // ---- load A (agg), split hi/lo: 64 rows ----
    const float4* agg4 = (const float4*)g_agg;
#pragma unroll
    for (int it = 0; it < 8; it++) {
        int idx = tid + it * 256;
        int row = idx >> 5, k4 = idx & 31;
        int gr = node0 + row;
        float4 v = make_float4(0.f, 0.f, 0.f, 0.f);
        if (gr < N_NODES) v = agg4[(size_t)gr * 32 + k4];
        __nv_bfloat16 h0 = __float2bfloat16(v.x), h1 = __float2bfloat16(v.y);
        __nv_bfloat16 h2 = __float2bfloat16(v.z), h3 = __float2bfloat16(v.w);
        __nv_bfloat16 l0 = __float2bfloat16(v.x - __bfloat162float(h0));
        __nv_bfloat16 l1 = __float2bfloat16(v.y - __bfloat162float(h1));
        __nv_bfloat16 l2 = __float2bfloat16(v.z - __bfloat162float(h2));
        __nv_bfloat16 l3 = __float2bfloat16(v.w - __bfloat162float(h3));
        size_t off = ((size_t)row * SA + k4 * 4) * 2;
        *(uint2*)(pAhi + off) = make_uint2(pk(h0, h1), pk(h2, h3));
        *(uint2*)(pAlo + off) = make_uint2(pk(l0, l1), pk(l2, l3));
    }

    const size_t istr = (size_t)HID * SA;
    const size_t lstr = (size_t)2 * LAYERS * HID * SA;
    // ---- stage W1 (hi/lo) ----
    {
        const float4* sh = (const float4*)(g_wt + (size_t)l * istr);
        const float4* sl = (const float4*)(g_wt + lstr + (size_t)l * istr);
        float4* dh = (float4*)pWh; float4* dl = (float4*)pWl;
        for (int i = tid; i < WTILE_B / 16; i += 256) { dh[i] = sh[i]; dl[i] = sl[i]; }
    }
    __syncthreads();

    // warp tiling: 8 warps -> (2 m) x (4 n); warp tile 32x32
    int m0 = (warp >> 2) * 32;
    int n0 = (warp & 3) * 32;
    int g = lane >> 3;
    int arow_off = (lane & 7) + ((g & 1) << 3);
    int akoff    = (g >> 1) << 3;
    int brow_off = (lane & 7) + ((g >> 1) << 3);
    int bkoff    = (g & 1) << 3;

    float acc[2][4][4];
#pragma unroll
    for (int s = 0; s < 2; s++)
#pragma unroll
        for (int j = 0; j < 4; j++)
#pragma unroll
            for (int c = 0; c < 4; c++) acc[s][j][c] = 0.f;

    // ---- GEMM 1 ----
    gemm_warp(aAhi, aAlo, aWh, aWl, m0, n0, arow_off, akoff, brow_off, bkoff, acc);
    __syncthreads();   // all warps done reading A & W1 before overwrite

    // ---- epilogue 1: h = relu(acc + b1) -> A tiles (hi/lo) ----
    {
        int r0 = m0 + (lane >> 2);
#pragma unroll
        for (int j = 0; j < 4; j++) {
            int col = n0 + j * 8 + (lane & 3) * 2;
            float bj0 = __ldg(b1 + col), bj1 = __ldg(b1 + col + 1);
#pragma unroll
            for (int s = 0; s < 2; s++) {
                int rA = r0 + s * 16, rB = rA + 8;
                float v0 = fmaxf(acc[s][j][0] + bj0, 0.f);
                float v1 = fmaxf(acc[s][j][1] + bj1, 0.f);
                float v2 = fmaxf(acc[s][j][2] + bj0, 0.f);
                float v3 = fmaxf(acc[s][j][3] + bj1, 0.f);
                __nv_bfloat16 h0 = __float2bfloat16(v0), h1 = __float2bfloat16(v1);
                __nv_bfloat16 h2 = __float2bfloat16(v2), h3 = __float2bfloat16(v3);
                __nv_bfloat16 q0 = __float2bfloat16(v0 - __bfloat162float(h0));
                __nv_bfloat16 q1 = __float2bfloat16(v1 - __bfloat162float(h1));
                __nv_bfloat16 q2 = __float2bfloat16(v2 - __bfloat162float(h2));
                __nv_bfloat16 q3 = __float2bfloat16(v3 - __bfloat162float(h3));
                size_t oA = ((size_t)rA * SA + col) * 2;
                size_t oB = ((size_t)rB * SA + col) * 2;
                *(uint32_t*)(pAhi + oA) = pk(h0, h1);
                *(uint32_t*)(pAlo + oA) = pk(q0, q1);
                *(uint32_t*)(pAhi + oB) = pk(h2, h3);
                *(uint32_t*)(pAlo + oB) = pk(q2, q3);
            }
        }
    }
    // ---- stage W2 over W1 (disjoint smem from H writes) ----
    {
        const float4* sh = (const float4*)(g_wt + (size_t)(LAYERS + l) * istr);
        const float4* sl = (const float4*)(g_wt + lstr + (size_t)(LAYERS + l) * istr);
        float4* dh = (float4*)pWh; float4* dl = (float4*)pWl;
        for (int i = tid; i < WTILE_B / 16; i += 256) { dh[i] = sh[i]; dl[i] = sl[i]; }
    }
    __syncthreads();

#pragma unroll
    for (int s = 0; s < 2; s++)
#pragma unroll
        for (int j = 0; j < 4; j++)
#pragma unroll
            for (int c = 0; c < 4; c++) acc[s][j][c] = 0.f;

    // ---- GEMM 2 ----
    gemm_warp(aAhi, aAlo, aWh, aWl, m0, n0, arow_off, akoff, brow_off, bkoff, acc);
    __syncthreads();   // fp32 stage reuses A region

    // ---- epilogue 2: relu(acc + b2) -> fp32 stage ----
    float* stage = (float*)S;    // 64 x 132 fp32 = 33792 B <= 2*ATILE_B
    {
        int r0 = m0 + (lane >> 2);
#pragma unroll
        for (int j = 0; j < 4; j++) {
            int col = n0 + j * 8 + (lane & 3) * 2;
            float bj0 = __ldg(b2 + col), bj1 = __ldg(b2 + col + 1);
#pragma unroll
            for (int s = 0; s < 2; s++) {
                int rA = r0 + s * 16, rB = rA + 8;
                stage[rA * 132 + col]     = fmaxf(acc[s][j][0] + bj0, 0.f);
                stage[rA * 132 + col + 1] = fmaxf(acc[s][j][1] + bj1, 0.f);
                stage[rB * 132 + col]     = fmaxf(acc[s][j][2] + bj0, 0.f);
                stage[rB * 132 + col + 1] = fmaxf(acc[s][j][3] + bj1, 0.f);
            }
        }
    }
    __syncthreads();

    // ---- coalesced writeback (x only; gather rebuilds agg) ----
    float4* x4 = (float4*)g_x;
#pragma unroll
    for (int it = 0; it < 8; it++) {
        int idx = tid + it * 256;
        int row = idx >> 5, k4 = idx & 31;
        int gr = node0 + row;
        if (gr < N_NODES)
            x4[(size_t)gr * 32 + k4] = *(float4*)&stage[row * 132 + k4 * 4];
    }
}

// ---------------------------------------------------------------------------
// Global mean pool
// ---------------------------------------------------------------------------
__global__ void pool_kernel(const int* __restrict__ batch,
                            float* __restrict__ out) {
    int g = blockIdx.x;
    __shared__ int s_range[2];
    if (threadIdx.x == 0) {
        int lo = 0, hi = N_NODES;
        while (lo < hi) { int m = (lo + hi) >> 1; if (batch[m] < g) lo = m + 1; else hi = m; }
        s_range[0] = lo;
        lo = 0; hi = N_NODES;
        while (lo < hi) { int m = (lo + hi) >> 1; if (batch[m] < g + 1) lo = m + 1; else hi = m; }
        s_range[1] = lo;
    }
    __syncthreads();
    int start = s_range[0], end = s_range[1];
    float sum = 0.f;
    for (int n = start; n < end; n++)
        sum += g_x[(size_t)n * HID + threadIdx.x];
    float cnt = (float)(end - start);
    out[g * HID + threadIdx.x] = sum / fmaxf(cnt, 1.0f);
}

// ---------------------------------------------------------------------------
// Inputs: x_tokens, edge_index, batch, emb, W1, b1, W2, b2
// ---------------------------------------------------------------------------
extern "C" void kernel_launch(void* const* d_in, const int* in_sizes, int n_in,
                              void* d_out, int out_size) {
    const int*   tok   = (const int*)  d_in[0];
    const int*   ei    = (const int*)  d_in[1];
    const int*   batch = (const int*)  d_in[2];
    const float* emb   = (const float*)d_in[3];
    const float* W1    = (const float*)d_in[4];
    const float* b1    = (const float*)d_in[5];
    const float* W2    = (const float*)d_in[6];
    const float* b2    = (const float*)d_in[7];
    float* out = (float*)d_out;

    cudaFuncSetAttribute(mlp_mma, cudaFuncAttributeMaxDynamicSharedMemorySize,
                         SMEM_BYTES);

    prep_w<<<(2 * LAYERS * HID * HID + 255) / 256, 256>>>(W1, W2);
    embed_kernel<<<(N_NODES * 32 + 255) / 256, 256>>>(tok, emb);

    // CSR build (once per launch, replayed in graph)
    k_zero <<<(N_NODES + 255) / 256, 256>>>();
    k_hist <<<(N_EDGES + 255) / 256, 256>>>(ei);
    k_scan1<<<SCAN_NB, SCAN_B>>>();
    k_scan2<<<1, 32>>>();
    k_scan3<<<(N_NODES + 255) / 256, 256>>>();
    k_fill <<<(N_EDGES + 255) / 256, 256>>>(ei);

    for (int l = 0; l < LAYERS; l++) {
        gather_kernel<<<(N_NODES * 32 + 255) / 256, 256>>>();
        mlp_mma<<<(N_NODES + NODES_PB - 1) / NODES_PB, 256, SMEM_BYTES>>>(
            b1 + (size_t)l * HID, b2 + (size_t)l * HID, l);
    }

    pool_kernel<<<N_GRAPHS, HID>>>(batch, out);
}

// round 7
// speedup vs baseline: 1.5173x; 1.5173x over previous
#include <cuda_runtime.h>
#include <cuda_bf16.h>
#include <cstdint>

#define N_NODES  100000
#define N_PAD    100096            // 1564 * 64
#define N_EDGES  600000
#define N_GRAPHS 2000
#define HID      128
#define LAYERS   6
#define SA       136               // bf16 row stride in smem (272 B)
#define NODES_PT 64                // nodes per tile
#define NT       (N_PAD / NODES_PT)  // 1564 tiles
#define NBLK     148
#define SCAN_B   1024
#define SCAN_NB  ((N_NODES + SCAN_B - 1) / SCAN_B)

// ---------------------------------------------------------------------------
// Persistent scratch (allocation-free)
// ---------------------------------------------------------------------------
__device__ float g_x[(size_t)N_NODES * HID];
__device__ __align__(16) __nv_bfloat16 g_aggh[(size_t)N_PAD * HID];  // pad rows stay 0
__device__ __align__(16) __nv_bfloat16 g_aggl[(size_t)N_PAD * HID];
__device__ __align__(16) __nv_bfloat16 g_wt[(size_t)2 * 2 * LAYERS * HID * SA];
// CSR scratch
__device__ int g_deg[N_NODES];
__device__ int g_rowstart[N_NODES + 1];
__device__ int g_cursor[N_NODES];
__device__ int g_blocksum[SCAN_NB];
__device__ int g_csr[N_EDGES];

// ---------------------------------------------------------------------------
// helpers
// ---------------------------------------------------------------------------
__device__ __forceinline__ uint32_t smem_u32(const void* p) {
    uint32_t a;
    asm("{ .reg .u64 t; cvta.to.shared.u64 t, %1; cvt.u32.u64 %0, t; }"
        : "=r"(a) : "l"(p));
    return a;
}
__device__ __forceinline__ void ldm_x4(uint32_t (&r)[4], uint32_t addr) {
    asm volatile("ldmatrix.sync.aligned.m8n8.x4.shared.b16 {%0,%1,%2,%3}, [%4];"
                 : "=r"(r[0]), "=r"(r[1]), "=r"(r[2]), "=r"(r[3]) : "r"(addr));
}
__device__ __forceinline__ void mma16816(float (&d)[4], const uint32_t (&a)[4],
                                         uint32_t b0, uint32_t b1) {
    asm volatile(
        "mma.sync.aligned.m16n8k16.row.col.f32.bf16.bf16.f32 "
        "{%0,%1,%2,%3}, {%4,%5,%6,%7}, {%8,%9}, {%0,%1,%2,%3};"
        : "+f"(d[0]), "+f"(d[1]), "+f"(d[2]), "+f"(d[3])
        : "r"(a[0]), "r"(a[1]), "r"(a[2]), "r"(a[3]), "r"(b0), "r"(b1));
}
__device__ __forceinline__ uint32_t pk(__nv_bfloat16 a, __nv_bfloat16 b) {
    return (uint32_t)__bfloat16_as_ushort(a) |
           ((uint32_t)__bfloat16_as_ushort(b) << 16);
}
#define CP16(dst, src) \
    asm volatile("cp.async.cg.shared.global [%0], [%1], 16;" \
                 :: "r"(dst), "l"(src) : "memory")
#define CP_COMMIT()  asm volatile("cp.async.commit_group;" ::: "memory")
#define CP_WAIT(n)   asm volatile("cp.async.wait_group %0;" :: "n"(n) : "memory")

// ---------------------------------------------------------------------------
// Embedding lookup
// ---------------------------------------------------------------------------
__global__ void embed_kernel(const int* __restrict__ tok,
                             const float* __restrict__ emb) {
    int i = blockIdx.x * blockDim.x + threadIdx.x;
    if (i >= N_NODES * 32) return;
    int node = i >> 5, d = i & 31;
    ((float4*)g_x)[i] = ((const float4*)emb)[tok[node] * 32 + d];
}

// ---------------------------------------------------------------------------
// CSR build
// ---------------------------------------------------------------------------
__global__ void k_zero() {
    int i = blockIdx.x * blockDim.x + threadIdx.x;
    if (i < N_NODES) g_deg[i] = 0;
}
__global__ void k_hist(const int* __restrict__ ei) {
    int i = blockIdx.x * blockDim.x + threadIdx.x;
    if (i < N_EDGES) atomicAdd(&g_deg[ei[N_EDGES + i]], 1);
}
__global__ void k_scan1() {
    __shared__ int sm[SCAN_B];
    int tid = threadIdx.x;
    int i = blockIdx.x * SCAN_B + tid;
    int v = (i < N_NODES) ? g_deg[i] : 0;
    sm[tid] = v;
    __syncthreads();
#pragma unroll
    for (int o = 1; o < SCAN_B; o <<= 1) {
        int t = (tid >= o) ? sm[tid - o] : 0;
        __syncthreads();
        sm[tid] += t;
        __syncthreads();
    }
    if (i < N_NODES) g_rowstart[i] = sm[tid] - v;
    if (tid == SCAN_B - 1) g_blocksum[blockIdx.x] = sm[tid];
}
__global__ void k_scan2() {
    if (threadIdx.x == 0) {
        int run = 0;
        for (int b = 0; b < SCAN_NB; b++) {
            int t = g_blocksum[b];
            g_blocksum[b] = run;
            run += t;
        }
        g_rowstart[N_NODES] = run;
    }
}
__global__ void k_scan3() {
    int i = blockIdx.x * blockDim.x + threadIdx.x;
    if (i < N_NODES) {
        int r = g_rowstart[i] + g_blocksum[i / SCAN_B];
        g_rowstart[i] = r;
        g_cursor[i] = r;
    }
}
__global__ void k_fill(const int* __restrict__ ei) {
    int i = blockIdx.x * blockDim.x + threadIdx.x;
    if (i < N_EDGES) {
        int dst = ei[N_EDGES + i];
        g_csr[atomicAdd(&g_cursor[dst], 1)] = ei[i];
    }
}

// ---------------------------------------------------------------------------
// Gather: agg[n] = x[n] + sum_{e} x[csr[e]]; writes pre-split bf16 hi/lo.
// ---------------------------------------------------------------------------
__global__ void gather_kernel() {
    int w = (blockIdx.x * blockDim.x + threadIdx.x) >> 5;
    int lane = threadIdx.x & 31;
    if (w >= N_NODES) return;
    int s = __ldg(g_rowstart + w), e = __ldg(g_rowstart + w + 1);
    const float4* x4 = (const float4*)g_x;
    float4 v = x4[(size_t)w * 32 + lane];
    for (int i = s; i < e; i++) {
        int src = __ldg(g_csr + i);
        float4 u = x4[(size_t)src * 32 + lane];
        v.x += u.x; v.y += u.y; v.z += u.z; v.w += u.w;
    }
    __nv_bfloat16 h0 = __float2bfloat16(v.x), h1 = __float2bfloat16(v.y);
    __nv_bfloat16 h2 = __float2bfloat16(v.z), h3 = __float2bfloat16(v.w);
    __nv_bfloat16 l0 = __float2bfloat16(v.x - __bfloat162float(h0));
    __nv_bfloat16 l1 = __float2bfloat16(v.y - __bfloat162float(h1));
    __nv_bfloat16 l2 = __float2bfloat16(v.z - __bfloat162float(h2));
    __nv_bfloat16 l3 = __float2bfloat16(v.w - __bfloat162float(h3));
    size_t off = (size_t)w * HID + lane * 4;
    *(uint2*)(g_aggh + off) = make_uint2(pk(h0, h1), pk(h2, h3));
    *(uint2*)(g_aggl + off) = make_uint2(pk(l0, l1), pk(l2, l3));
}

// ---------------------------------------------------------------------------
// Weight prep: split W[k][c] -> transposed hi/lo images Wt[c][k], stride SA.
// ---------------------------------------------------------------------------
__global__ void prep_w(const float* __restrict__ W1, const float* __restrict__ W2) {
    int i = blockIdx.x * blockDim.x + threadIdx.x;
    if (i >= 2 * LAYERS * HID * HID) return;
    int which = i / (LAYERS * HID * HID);
    int r = i % (LAYERS * HID * HID);
    int l = r / (HID * HID);
    int kc = r % (HID * HID);
    int k = kc / HID, c = kc % HID;
    const float* W = which ? W2 : W1;
    float v = W[(size_t)l * HID * HID + k * HID + c];
    __nv_bfloat16 hi = __float2bfloat16(v);
    __nv_bfloat16 lo = __float2bfloat16(v - __bfloat162float(hi));
    size_t img = (size_t)which * LAYERS + l;
    size_t o = img * HID * SA + (size_t)c * SA + k;
    g_wt[o] = hi;
    g_wt[(size_t)2 * LAYERS * HID * SA + o] = lo;
}

// ---------------------------------------------------------------------------
// Persistent fused GIN MLP.
// smem: [W1h][W1l][W2h][W2l] (4 x 34816) + A bufs [2][hi 17408 | lo 17408]
// ---------------------------------------------------------------------------
#define WTILE_B   (HID * SA * 2)          // 34816
#define AHALF_B   (NODES_PT * SA * 2)     // 17408
#define ABUF_B    (2 * AHALF_B)           // 34816
#define SMEM_BYTES (4 * WTILE_B + 2 * ABUF_B)  // 208896

__device__ __forceinline__ void prefetch_tile(uint32_t dstbase, int node0, int tid) {
#pragma unroll
    for (int c = tid; c < 2048; c += 256) {
        int half = c >> 10;                 // 0: hi, 1: lo
        int r = (c & 1023) >> 4;
        int o = c & 15;
        const __nv_bfloat16* src =
            (half ? g_aggl : g_aggh) + ((size_t)(node0 + r) << 7) + (o << 3);
        uint32_t dst = dstbase + half * AHALF_B + r * (SA * 2) + o * 16;
        CP16(dst, src);
    }
}

// 3-product split GEMM over a 32x32 warp tile.
__device__ __forceinline__ void gemm_warp(
    uint32_t aAhi, uint32_t aAlo, uint32_t aWh, uint32_t aWl,
    int m0, int n0, int arow_off, int akoff, int brow_off, int bkoff,
    float (&acc)[2][4][4])
{
#pragma unroll
    for (int kb = 0; kb < HID; kb += 16) {
        uint32_t ah[2][4], al[2][4];
#pragma unroll
        for (int s = 0; s < 2; s++) {
            uint32_t ro = (uint32_t)((m0 + s * 16 + arow_off) * SA + kb + akoff) * 2;
            ldm_x4(ah[s], aAhi + ro);
            ldm_x4(al[s], aAlo + ro);
        }
#pragma unroll
        for (int nb = 0; nb < 2; nb++) {
            uint32_t bh[4], bl[4];
            uint32_t ro = (uint32_t)((n0 + nb * 16 + brow_off) * SA + kb + bkoff) * 2;
            ldm_x4(bh, aWh + ro);
            ldm_x4(bl, aWl + ro);
#pragma unroll
            for (int s = 0; s < 2; s++) {
                mma16816(acc[s][2 * nb],     ah[s], bh[0], bh[1]);
                mma16816(acc[s][2 * nb],     ah[s], bl[0], bl[1]);
                mma16816(acc[s][2 * nb],     al[s], bh[0], bh[1]);
                mma16816(acc[s][2 * nb + 1], ah[s], bh[2], bh[3]);
                mma16816(acc[s][2 * nb + 1], ah[s], bl[2], bl[3]);
                mma16816(acc[s][2 * nb + 1], al[s], bh[2], bh[3]);
            }
        }
    }
}

__global__ void __launch_bounds__(256, 1) mlp_mma(
    const float* __restrict__ b1, const float* __restrict__ b2, int l)
{
    extern __shared__ __align__(16) char S[];
    uint32_t base = smem_u32(S);
    uint32_t aW1h = base, aW1l = base + WTILE_B;
    uint32_t aW2h = base + 2 * WTILE_B, aW2l = base + 3 * WTILE_B;
    uint32_t aBuf[2] = { base + 4 * WTILE_B, base + 4 * WTILE_B + ABUF_B };
    char* pBuf[2] = { S + 4 * WTILE_B, S + 4 * WTILE_B + ABUF_B };

    int tid = threadIdx.x, warp = tid >> 5, lane = tid & 31;

    // ---- stage all weights once ----
    {
        const size_t istr = (size_t)HID * SA;
        const size_t lstr = (size_t)2 * LAYERS * HID * SA;
        const float4* srcs[4] = {
            (const float4*)(g_wt + (size_t)l * istr),
            (const float4*)(g_wt + lstr + (size_t)l * istr),
            (const float4*)(g_wt + (size_t)(LAYERS + l) * istr),
            (const float4*)(g_wt + lstr + (size_t)(LAYERS + l) * istr) };
#pragma unroll
        for (int q = 0; q < 4; q++) {
            float4* d = (float4*)(S + q * WTILE_B);
            for (int i = tid; i < WTILE_B / 16; i += 256) d[i] = srcs[q][i];
        }
    }

    // warp tiling: 8 warps -> (2 m) x (4 n); warp tile 32x32
    int m0 = (warp >> 2) * 32;
    int n0 = (warp & 3) * 32;
    int g = lane >> 3;
    int arow_off = (lane & 7) + ((g & 1) << 3);
    int akoff    = (g >> 1) << 3;
    int brow_off = (lane & 7) + ((g >> 1) << 3);
    int bkoff    = (g & 1) << 3;

    int bid = blockIdx.x;
    prefetch_tile(aBuf[0], bid * NODES_PT, tid);
    CP_COMMIT();
    __syncthreads();   // weights staged

    int it = 0;
    for (int t = bid; t < NT; t += NBLK, it++) {
        int cur = it & 1;
        int node0 = t * NODES_PT;
        int tn = t + NBLK;
        if (tn < NT) {
            prefetch_tile(aBuf[1 - cur], tn * NODES_PT, tid);
            CP_COMMIT();
            CP_WAIT(1);
        } else {
            CP_WAIT(0);
        }
        __syncthreads();   // tile t resident

        uint32_t aAhi = aBuf[cur], aAlo = aBuf[cur] + AHALF_B;
        char* pA = pBuf[cur];

        float acc[2][4][4];
#pragma unroll
        for (int s = 0; s < 2; s++)
#pragma unroll
            for (int j = 0; j < 4; j++)
#pragma unroll
                for (int c = 0; c < 4; c++) acc[s][j][c] = 0.f;

        // ---- GEMM 1 ----
        gemm_warp(aAhi, aAlo, aW1h, aW1l, m0, n0,
                  arow_off, akoff, brow_off, bkoff, acc);
        __syncthreads();   // everyone done reading A before overwrite

        // ---- epilogue 1: h = relu(acc + b1) -> A buf (hi/lo) ----
        {
            int r0 = m0 + (lane >> 2);
#pragma unroll
            for (int j = 0; j < 4; j++) {
                int col = n0 + j * 8 + (lane & 3) * 2;
                float bj0 = __ldg(b1 + col), bj1 = __ldg(b1 + col + 1);
#pragma unroll
                for (int s = 0; s < 2; s++) {
                    int rA = r0 + s * 16, rB = rA + 8;
                    float v0 = fmaxf(acc[s][j][0] + bj0, 0.f);
                    float v1 = fmaxf(acc[s][j][1] + bj1, 0.f);
                    float v2 = fmaxf(acc[s][j][2] + bj0, 0.f);
                    float v3 = fmaxf(acc[s][j][3] + bj1, 0.f);
                    __nv_bfloat16 h0 = __float2bfloat16(v0), h1 = __float2bfloat16(v1);
                    __nv_bfloat16 h2 = __float2bfloat16(v2), h3 = __float2bfloat16(v3);
                    __nv_bfloat16 q0 = __float2bfloat16(v0 - __bfloat162float(h0));
                    __nv_bfloat16 q1 = __float2bfloat16(v1 - __bfloat162float(h1));
                    __nv_bfloat16 q2 = __float2bfloat16(v2 - __bfloat162float(h2));
                    __nv_bfloat16 q3 = __float2bfloat16(v3 - __bfloat162float(h3));
                    uint32_t oA = (uint32_t)(rA * SA + col) * 2;
                    uint32_t oB = (uint32_t)(rB * SA + col) * 2;
                    *(uint32_t*)(pA + oA) = pk(h0, h1);
                    *(uint32_t*)(pA + AHALF_B + oA) = pk(q0, q1);
                    *(uint32_t*)(pA + oB) = pk(h2, h3);
                    *(uint32_t*)(pA + AHALF_B + oB) = pk(q2, q3);
                }
            }
        }
        __syncthreads();

#pragma unroll
        for (int s = 0; s < 2; s++)
#pragma unroll
            for (int j = 0; j < 4; j++)
#pragma unroll
                for (int c = 0; c < 4; c++) acc[s][j][c] = 0.f;

        // ---- GEMM 2 ----
        gemm_warp(aAhi, aAlo, aW2h, aW2l, m0, n0,
                  arow_off, akoff, brow_off, bkoff, acc);

        // ---- epilogue 2: relu(acc + b2) -> g_x directly ----
        {
            int r0 = m0 + (lane >> 2);
#pragma unroll
            for (int j = 0; j < 4; j++) {
                int col = n0 + j * 8 + (lane & 3) * 2;
                float bj0 = __ldg(b2 + col), bj1 = __ldg(b2 + col + 1);
#pragma unroll
                for (int s = 0; s < 2; s++) {
                    int rA = r0 + s * 16, rB = rA + 8;
                    int gA = node0 + rA, gB = node0 + rB;
                    if (gA < N_NODES) {
                        float2 v = make_float2(fmaxf(acc[s][j][0] + bj0, 0.f),
                                               fmaxf(acc[s][j][1] + bj1, 0.f));
                        *(float2*)(g_x + (size_t)gA * HID + col) = v;
                    }
                    if (gB < N_NODES) {
                        float2 v = make_float2(fmaxf(acc[s][j][2] + bj0, 0.f),
                                               fmaxf(acc[s][j][3] + bj1, 0.f));
                        *(float2*)(g_x + (size_t)gB * HID + col) = v;
                    }
                }
            }
        }
        __syncthreads();   // A buf must be fully read before next prefetch overwrites
    }
}

// ---------------------------------------------------------------------------
// Global mean pool
// ---------------------------------------------------------------------------
__global__ void pool_kernel(const int* __restrict__ batch,
                            float* __restrict__ out) {
    int g = blockIdx.x;
    __shared__ int s_range[2];
    if (threadIdx.x == 0) {
        int lo = 0, hi = N_NODES;
        while (lo < hi) { int m = (lo + hi) >> 1; if (batch[m] < g) lo = m + 1; else hi = m; }
        s_range[0] = lo;
        lo = 0; hi = N_NODES;
        while (lo < hi) { int m = (lo + hi) >> 1; if (batch[m] < g + 1) lo = m + 1; else hi = m; }
        s_range[1] = lo;
    }
    __syncthreads();
    int start = s_range[0], end = s_range[1];
    float sum = 0.f;
    for (int n = start; n < end; n++)
        sum += g_x[(size_t)n * HID + threadIdx.x];
    float cnt = (float)(end - start);
    out[g * HID + threadIdx.x] = sum / fmaxf(cnt, 1.0f);
}

// ---------------------------------------------------------------------------
// Inputs: x_tokens, edge_index, batch, emb, W1, b1, W2, b2
// ---------------------------------------------------------------------------
extern "C" void kernel_launch(void* const* d_in, const int* in_sizes, int n_in,
                              void* d_out, int out_size) {
    const int*   tok   = (const int*)  d_in[0];
    const int*   ei    = (const int*)  d_in[1];
    const int*   batch = (const int*)  d_in[2];
    const float* emb   = (const float*)d_in[3];
    const float* W1    = (const float*)d_in[4];
    const float* b1    = (const float*)d_in[5];
    const float* W2    = (const float*)d_in[6];
    const float* b2    = (const float*)d_in[7];
    float* out = (float*)d_out;

    cudaFuncSetAttribute(mlp_mma, cudaFuncAttributeMaxDynamicSharedMemorySize,
                         SMEM_BYTES);

    prep_w<<<(2 * LAYERS * HID * HID + 255) / 256, 256>>>(W1, W2);
    embed_kernel<<<(N_NODES * 32 + 255) / 256, 256>>>(tok, emb);

    k_zero <<<(N_NODES + 255) / 256, 256>>>();
    k_hist <<<(N_EDGES + 255) / 256, 256>>>(ei);
    k_scan1<<<SCAN_NB, SCAN_B>>>();
    k_scan2<<<1, 32>>>();
    k_scan3<<<(N_NODES + 255) / 256, 256>>>();
    k_fill <<<(N_EDGES + 255) / 256, 256>>>(ei);

    for (int l = 0; l < LAYERS; l++) {
        gather_kernel<<<(N_NODES * 32 + 255) / 256, 256>>>();
        mlp_mma<<<NBLK, 256, SMEM_BYTES>>>(
            b1 + (size_t)l * HID, b2 + (size_t)l * HID, l);
    }

    pool_kernel<<<N_GRAPHS, HID>>>(batch, out);
}